// round 2
// baseline (speedup 1.0000x reference)
#include <cuda_runtime.h>
#include <cstdint>

#define BB 2
#define HH 16
#define SS 2048
#define DH 128

#define BM 128
#define BN 64
#define NTHREADS 256
#define NITER (SS / BN)      // 32
#define NSTILE (SS / BM)     // 16

// Shared-memory row strides (floats), chosen bank-conflict-free for the
// fragment LDS patterns (QS=136: bank = 8g+t all-distinct; PS/MS=68: 4g+t).
#define QS 136
#define MS 68
#define PS 68

#define SQ_OFF  0
#define SK_OFF  (SQ_OFF + BM * QS)
#define SV_OFF  (SK_OFF + BN * QS)
#define SM_OFF  (SV_OFF + BN * QS)
#define SP_OFF  (SM_OFF + BM * MS)
#define SR_OFF  (SP_OFF + BM * PS)
#define SMEM_FLOATS (SR_OFF + 2 * BM)
#define SMEM_BYTES  (SMEM_FLOATS * 4)   // 209,920 B

__device__ __forceinline__ uint32_t f2tf32(float x) {
    uint32_t u;
    asm("cvt.rna.tf32.f32 %0, %1;" : "=r"(u) : "f"(x));
    return u;
}
__device__ __forceinline__ float tf32rf(float x) { return __uint_as_float(f2tf32(x)); }

__device__ __forceinline__ void mma8(float* c,
                                     uint32_t a0, uint32_t a1, uint32_t a2, uint32_t a3,
                                     uint32_t b0, uint32_t b1) {
    asm volatile(
        "mma.sync.aligned.m16n8k8.row.col.f32.tf32.tf32.f32 "
        "{%0,%1,%2,%3}, {%4,%5,%6,%7}, {%8,%9}, {%0,%1,%2,%3};\n"
        : "+f"(c[0]), "+f"(c[1]), "+f"(c[2]), "+f"(c[3])
        : "r"(a0), "r"(a1), "r"(a2), "r"(a3), "r"(b0), "r"(b1));
}

__global__ __launch_bounds__(NTHREADS, 1)
void retatt_kernel(const float* __restrict__ q, const float* __restrict__ k,
                   const float* __restrict__ v, const float* __restrict__ mask,
                   float* __restrict__ o)
{
    extern __shared__ float smem[];
    float* sQ = smem + SQ_OFF;
    float* sK = smem + SK_OFF;
    float* sV = smem + SV_OFF;
    float* sM = smem + SM_OFF;
    float* sP = smem + SP_OFF;
    float* sR = smem + SR_OFF;

    // b fastest (both batches share the mask tile via L2), then s-tile, then head.
    const int bid = blockIdx.x;
    const int b  = bid & 1;
    const int r_ = bid >> 1;
    const int h  = r_ / NSTILE;
    const int st = r_ % NSTILE;
    const int s0 = st * BM;

    const int tid  = threadIdx.x;
    const int wid  = tid >> 5;
    const int lane = tid & 31;
    const int g = lane >> 2;
    const int t = lane & 3;
    const int wm = wid >> 1;     // 0..3 -> 32-row strip
    const int wn = wid & 1;      // 0..1 -> 32-col (GEMM1) / 64-col (GEMM2) strip
    const int m_base = wm * 32;
    const int n_base = wn * 32;
    const int d_base = wn * 64;

    const float* qbase = q + ((size_t)(b * HH + h) * SS + s0) * DH;
    const float* kbase = k + ((size_t)(b * HH + h) * SS) * DH;
    const float* vbase = v + ((size_t)(b * HH + h) * SS) * DH;
    const float* mbase = mask + ((size_t)h * SS + s0) * SS;

    // Q tile [BM, DH] once, tf32-rounded
    {
        const float4* gq = (const float4*)qbase;
        #pragma unroll
        for (int it = 0; it < (BM * DH / 4) / NTHREADS; ++it) {
            int f = tid + it * NTHREADS;
            float4 val = gq[f];
            int row = f >> 5;
            int d = (f & 31) << 2;
            *(float4*)&sQ[row * QS + d] =
                make_float4(tf32rf(val.x), tf32rf(val.y), tf32rf(val.z), tf32rf(val.w));
        }
    }

    float acc2[2][8][4];
    #pragma unroll
    for (int mt = 0; mt < 2; ++mt)
        #pragma unroll
        for (int nt = 0; nt < 8; ++nt)
            #pragma unroll
            for (int i = 0; i < 4; ++i) acc2[mt][nt][i] = 0.f;

    float rsum[2][2] = {{0.f, 0.f}, {0.f, 0.f}};

    for (int it = 0; it < NITER; ++it) {
        const int t0 = it * BN;
        __syncthreads();   // prior iteration done reading sK/sV/sM/sP

        {   // K tile [BN, DH]
            const float4* gk = (const float4*)(kbase + (size_t)t0 * DH);
            #pragma unroll
            for (int i = 0; i < (BN * DH / 4) / NTHREADS; ++i) {
                int f = tid + i * NTHREADS;
                float4 val = gk[f];
                int row = f >> 5;
                int d = (f & 31) << 2;
                *(float4*)&sK[row * QS + d] =
                    make_float4(tf32rf(val.x), tf32rf(val.y), tf32rf(val.z), tf32rf(val.w));
            }
        }
        {   // V tile [BN, DH]
            const float4* gv = (const float4*)(vbase + (size_t)t0 * DH);
            #pragma unroll
            for (int i = 0; i < (BN * DH / 4) / NTHREADS; ++i) {
                int f = tid + i * NTHREADS;
                float4 val = gv[f];
                int row = f >> 5;
                int d = (f & 31) << 2;
                *(float4*)&sV[row * QS + d] =
                    make_float4(tf32rf(val.x), tf32rf(val.y), tf32rf(val.z), tf32rf(val.w));
            }
        }
        {   // mask tile [BM, BN], full fp32
            #pragma unroll
            for (int i = 0; i < (BM * BN / 4) / NTHREADS; ++i) {
                int f = tid + i * NTHREADS;
                int row = f >> 4;
                int c = (f & 15) << 2;
                *(float4*)&sM[row * MS + c] = *(const float4*)(mbase + (size_t)row * SS + t0 + c);
            }
        }
        __syncthreads();

        // GEMM1: S = Q @ K^T (warp tile 32x32)
        float acc1[2][4][4];
        #pragma unroll
        for (int mt = 0; mt < 2; ++mt)
            #pragma unroll
            for (int nt = 0; nt < 4; ++nt)
                #pragma unroll
                for (int i = 0; i < 4; ++i) acc1[mt][nt][i] = 0.f;

        #pragma unroll
        for (int kk = 0; kk < DH / 8; ++kk) {
            uint32_t a[2][4];
            #pragma unroll
            for (int mt = 0; mt < 2; ++mt) {
                const float* qr0 = &sQ[(m_base + mt * 16 + g) * QS + kk * 8];
                const float* qr1 = qr0 + 8 * QS;
                a[mt][0] = __float_as_uint(qr0[t]);
                a[mt][1] = __float_as_uint(qr1[t]);
                a[mt][2] = __float_as_uint(qr0[t + 4]);
                a[mt][3] = __float_as_uint(qr1[t + 4]);
            }
            #pragma unroll
            for (int nt = 0; nt < 4; ++nt) {
                const float* kr = &sK[(n_base + nt * 8 + g) * QS + kk * 8];
                uint32_t b0 = __float_as_uint(kr[t]);
                uint32_t b1 = __float_as_uint(kr[t + 4]);
                mma8(acc1[0][nt], a[0][0], a[0][1], a[0][2], a[0][3], b0, b1);
                mma8(acc1[1][nt], a[1][0], a[1][1], a[1][2], a[1][3], b0, b1);
            }
        }

        // mask multiply (fp32), |.|-rowsum, P -> smem (tf32)
        #pragma unroll
        for (int mt = 0; mt < 2; ++mt) {
            #pragma unroll
            for (int nt = 0; nt < 4; ++nt) {
                int row0 = m_base + mt * 16 + g;
                int cb = n_base + nt * 8 + 2 * t;
                float2 m01 = *(const float2*)&sM[row0 * MS + cb];
                float2 m23 = *(const float2*)&sM[(row0 + 8) * MS + cb];
                float p0 = acc1[mt][nt][0] * m01.x;
                float p1 = acc1[mt][nt][1] * m01.y;
                float p2 = acc1[mt][nt][2] * m23.x;
                float p3 = acc1[mt][nt][3] * m23.y;
                rsum[mt][0] += fabsf(p0) + fabsf(p1);
                rsum[mt][1] += fabsf(p2) + fabsf(p3);
                sP[row0 * PS + cb]           = tf32rf(p0);
                sP[row0 * PS + cb + 1]       = tf32rf(p1);
                sP[(row0 + 8) * PS + cb]     = tf32rf(p2);
                sP[(row0 + 8) * PS + cb + 1] = tf32rf(p3);
            }
        }
        __syncthreads();

        // GEMM2: O += P @ V (warp tile 32x64)
        #pragma unroll
        for (int kk = 0; kk < BN / 8; ++kk) {
            uint32_t a[2][4];
            #pragma unroll
            for (int mt = 0; mt < 2; ++mt) {
                const float* pr0 = &sP[(m_base + mt * 16 + g) * PS + kk * 8];
                const float* pr1 = pr0 + 8 * PS;
                a[mt][0] = __float_as_uint(pr0[t]);
                a[mt][1] = __float_as_uint(pr1[t]);
                a[mt][2] = __float_as_uint(pr0[t + 4]);
                a[mt][3] = __float_as_uint(pr1[t + 4]);
            }
            #pragma unroll
            for (int nt = 0; nt < 8; ++nt) {
                const float* vr = &sV[(kk * 8 + t) * QS + d_base + nt * 8 + g];
                uint32_t b0 = __float_as_uint(vr[0]);
                uint32_t b1 = __float_as_uint(vr[4 * QS]);
                mma8(acc2[0][nt], a[0][0], a[0][1], a[0][2], a[0][3], b0, b1);
                mma8(acc2[1][nt], a[1][0], a[1][1], a[1][2], a[1][3], b0, b1);
            }
        }
    }

    // deterministic r reduction: quad shfl, then the two wn halves via smem
    #pragma unroll
    for (int mt = 0; mt < 2; ++mt) {
        #pragma unroll
        for (int half = 0; half < 2; ++half) {
            float vv = rsum[mt][half];
            vv += __shfl_xor_sync(0xffffffffu, vv, 1);
            vv += __shfl_xor_sync(0xffffffffu, vv, 2);
            if (t == 0)
                sR[wn * BM + m_base + mt * 16 + half * 8 + g] = vv;
        }
    }
    __syncthreads();

    float* ob = o + ((size_t)(b * HH + h) * SS + s0) * DH;
    #pragma unroll
    for (int mt = 0; mt < 2; ++mt) {
        int row0 = m_base + mt * 16 + g;
        float inv0 = 1.0f / fmaxf(sR[row0] + sR[BM + row0], 1.0f);
        float inv1 = 1.0f / fmaxf(sR[row0 + 8] + sR[BM + row0 + 8], 1.0f);
        #pragma unroll
        for (int nt = 0; nt < 8; ++nt) {
            int col = d_base + nt * 8 + 2 * t;
            *(float2*)&ob[(size_t)row0 * DH + col] =
                make_float2(acc2[mt][nt][0] * inv0, acc2[mt][nt][1] * inv0);
            *(float2*)&ob[(size_t)(row0 + 8) * DH + col] =
                make_float2(acc2[mt][nt][2] * inv1, acc2[mt][nt][3] * inv1);
        }
    }
}

extern "C" void kernel_launch(void* const* d_in, const int* in_sizes, int n_in,
                              void* d_out, int out_size) {
    const float* q = (const float*)d_in[0];
    const float* k = (const float*)d_in[1];
    const float* v = (const float*)d_in[2];
    const float* m = (const float*)d_in[3];
    float* o = (float*)d_out;
    cudaFuncSetAttribute(retatt_kernel,
                         cudaFuncAttributeMaxDynamicSharedMemorySize, SMEM_BYTES);
    retatt_kernel<<<BB * HH * NSTILE, NTHREADS, SMEM_BYTES>>>(q, k, v, m, o);
}

// round 4
// speedup vs baseline: 2.2145x; 2.2145x over previous
#include <cuda_runtime.h>
#include <cuda_fp16.h>
#include <cstdint>

#define BB 2
#define HH 16
#define SS 2048
#define DH 128
#define BM 128
#define BN 64
#define NITER 32
#define NSTILE 16
#define NTHREADS 512

// smem layout (bytes). Row strides padded for conflict-free ldmatrix:
// Q/K/V rows 272B (17*16B), P rows 144B (9*16B), mask rows 68 floats (272B).
#define QSB 272
#define PSB 144
#define MSF 68
#define SM_Q 0
#define SM_K 34816            // 2 bufs x 64*272 = 17408 each
#define SM_V 69632            // 2 bufs x 17408
#define SM_M 104448           // 2 bufs x 128*272 = 34816 each
#define SM_P 174080           // 128*144 = 18432
#define SM_R 192512           // 4*128 floats = 2048
#define SMEM_BYTES 194560

__device__ __forceinline__ uint32_t smem_u32(const void* p) {
    uint32_t a;
    asm("{ .reg .u64 t; cvta.to.shared.u64 t, %1; cvt.u32.u64 %0, t; }" : "=r"(a) : "l"(p));
    return a;
}
__device__ __forceinline__ void ldsm_x4(uint32_t& r0, uint32_t& r1, uint32_t& r2, uint32_t& r3, uint32_t a) {
    asm volatile("ldmatrix.sync.aligned.m8n8.x4.shared.b16 {%0,%1,%2,%3}, [%4];"
                 : "=r"(r0), "=r"(r1), "=r"(r2), "=r"(r3) : "r"(a));
}
__device__ __forceinline__ void ldsm_x4t(uint32_t& r0, uint32_t& r1, uint32_t& r2, uint32_t& r3, uint32_t a) {
    asm volatile("ldmatrix.sync.aligned.m8n8.x4.trans.shared.b16 {%0,%1,%2,%3}, [%4];"
                 : "=r"(r0), "=r"(r1), "=r"(r2), "=r"(r3) : "r"(a));
}
__device__ __forceinline__ void mma16816(float* c, uint32_t a0, uint32_t a1, uint32_t a2, uint32_t a3,
                                         uint32_t b0, uint32_t b1) {
    asm volatile(
        "mma.sync.aligned.m16n8k16.row.col.f32.f16.f16.f32 "
        "{%0,%1,%2,%3}, {%4,%5,%6,%7}, {%8,%9}, {%0,%1,%2,%3};"
        : "+f"(c[0]), "+f"(c[1]), "+f"(c[2]), "+f"(c[3])
        : "r"(a0), "r"(a1), "r"(a2), "r"(a3), "r"(b0), "r"(b1));
}
__device__ __forceinline__ void cpa16(uint32_t dst, const void* src) {
    asm volatile("cp.async.cg.shared.global [%0], [%1], 16;" :: "r"(dst), "l"(src) : "memory");
}
#define CPA_COMMIT asm volatile("cp.async.commit_group;" ::: "memory")
#define CPA_WAIT0  asm volatile("cp.async.wait_group 0;" ::: "memory")

// convert float4 -> uint2 (4 fp16)
__device__ __forceinline__ uint2 f4h4(float4 v) {
    __half2 a = __floats2half2_rn(v.x, v.y);
    __half2 b = __floats2half2_rn(v.z, v.w);
    uint2 w;
    w.x = *(uint32_t*)&a;
    w.y = *(uint32_t*)&b;
    return w;
}

__global__ __launch_bounds__(NTHREADS, 1)
void retatt_k4(const float* __restrict__ q, const float* __restrict__ k,
               const float* __restrict__ v, const float* __restrict__ mask,
               float* __restrict__ o)
{
    extern __shared__ char smem[];
    const uint32_t sbase = smem_u32(smem);
    const int tid = threadIdx.x;
    const int wid = tid >> 5;
    const int lane = tid & 31;
    const int g = lane >> 2;
    const int t = lane & 3;
    const int wm = wid >> 2;          // 0..3: 32-row strip
    const int wn = wid & 3;           // 0..3: 16 cols (G1) / 32 cols (G2)
    const int m_base = wm * 32;
    const int n_base = wn * 16;
    const int d_base = wn * 32;
    const int lrow = lane & 15;       // ldmatrix row within 16
    const int lchunk = (lane >> 4) * 16; // ldmatrix 16B column chunk

    const int bid = blockIdx.x;
    const int b  = bid & 1;
    const int r_ = bid >> 1;
    const int h  = r_ / NSTILE;
    const int st = r_ % NSTILE;
    const int s0 = st * BM;

    const float* qbase = q + ((size_t)(b * HH + h) * SS + s0) * DH;
    const float* kbase = k + ((size_t)(b * HH + h) * SS) * DH;
    const float* vbase = v + ((size_t)(b * HH + h) * SS) * DH;
    const float* mbase = mask + ((size_t)h * SS + s0) * SS;

    // ---- prologue: Q (fp16), K0/V0 (LDG->STS), mask0 (cp.async) ----
    {
        const float4* gq = (const float4*)qbase;
        #pragma unroll
        for (int i = 0; i < 8; ++i) {
            int f = tid + i * NTHREADS;
            int row = f >> 5, d = (f & 31) << 2;
            *(uint2*)(smem + SM_Q + row * QSB + d * 2) = f4h4(gq[f]);
        }
        const float4* gk = (const float4*)kbase;
        const float4* gv = (const float4*)vbase;
        #pragma unroll
        for (int i = 0; i < 4; ++i) {
            int f = tid + i * NTHREADS;
            int row = f >> 5, d = (f & 31) << 2;
            *(uint2*)(smem + SM_K + row * QSB + d * 2) = f4h4(gk[f]);
            *(uint2*)(smem + SM_V + row * QSB + d * 2) = f4h4(gv[f]);
        }
        #pragma unroll
        for (int i = 0; i < 4; ++i) {
            int f = tid + i * NTHREADS;
            int row = f >> 4, c = (f & 15) << 2;
            cpa16(sbase + SM_M + row * QSB + c * 4, mbase + (size_t)row * SS + c);
        }
        CPA_COMMIT;
        CPA_WAIT0;
        __syncthreads();
    }

    float acc2[2][4][4];
    #pragma unroll
    for (int mt = 0; mt < 2; ++mt)
        #pragma unroll
        for (int nt = 0; nt < 4; ++nt)
            #pragma unroll
            for (int i = 0; i < 4; ++i) acc2[mt][nt][i] = 0.f;
    float rsum[2][2] = {{0.f, 0.f}, {0.f, 0.f}};

    // per-thread ldmatrix base addresses
    const uint32_t qa_base = sbase + SM_Q + (uint32_t)(m_base + lrow) * QSB + lchunk;
    const uint32_t pa_base = sbase + SM_P + (uint32_t)(m_base + lrow) * PSB + lchunk;

    #pragma unroll 1
    for (int it = 0; it < NITER; ++it) {
        const int buf = it & 1;
        const uint32_t sKb = sbase + SM_K + buf * 17408;
        const uint32_t sVb = sbase + SM_V + buf * 17408;
        const float* mbuf = (const float*)(smem + SM_M + buf * 34816);

        // ---- issue next-tile loads (LDG to regs; mask via cp.async) ----
        float4 kst[4], vst[4];
        const bool more = (it + 1 < NITER);
        if (more) {
            const int t1 = (it + 1) * BN;
            const float4* gk = (const float4*)(kbase + (size_t)t1 * DH);
            const float4* gv = (const float4*)(vbase + (size_t)t1 * DH);
            #pragma unroll
            for (int i = 0; i < 4; ++i) {
                int f = tid + i * NTHREADS;
                kst[i] = gk[f];
                vst[i] = gv[f];
            }
            uint32_t mdst = sbase + SM_M + (buf ^ 1) * 34816;
            #pragma unroll
            for (int i = 0; i < 4; ++i) {
                int f = tid + i * NTHREADS;
                int row = f >> 4, c = (f & 15) << 2;
                cpa16(mdst + row * QSB + c * 4, mbase + (size_t)row * SS + t1 + c);
            }
            CPA_COMMIT;
        }

        // ---- GEMM1: S[128,64] = Q @ K^T ----
        float acc1[2][2][4];
        #pragma unroll
        for (int mt = 0; mt < 2; ++mt)
            #pragma unroll
            for (int nt = 0; nt < 2; ++nt)
                #pragma unroll
                for (int i = 0; i < 4; ++i) acc1[mt][nt][i] = 0.f;

        const uint32_t kb_base = sKb + (uint32_t)(n_base + lrow) * QSB + lchunk;
        #pragma unroll
        for (int kk = 0; kk < 8; ++kk) {
            uint32_t a0[4], a1[4], bb[4];
            ldsm_x4(a0[0], a0[1], a0[2], a0[3], qa_base + kk * 32);
            ldsm_x4(a1[0], a1[1], a1[2], a1[3], qa_base + 16 * QSB + kk * 32);
            ldsm_x4(bb[0], bb[1], bb[2], bb[3], kb_base + kk * 32);
            mma16816(acc1[0][0], a0[0], a0[1], a0[2], a0[3], bb[0], bb[2]);
            mma16816(acc1[0][1], a0[0], a0[1], a0[2], a0[3], bb[1], bb[3]);
            mma16816(acc1[1][0], a1[0], a1[1], a1[2], a1[3], bb[0], bb[2]);
            mma16816(acc1[1][1], a1[0], a1[1], a1[2], a1[3], bb[1], bb[3]);
        }

        // ---- epilogue: P = S * mask (fp16 to smem), rsum += |P| ----
        #pragma unroll
        for (int mt = 0; mt < 2; ++mt) {
            #pragma unroll
            for (int nt = 0; nt < 2; ++nt) {
                int row0 = m_base + mt * 16 + g;
                int cb = n_base + nt * 8 + 2 * t;
                float2 m0 = *(const float2*)&mbuf[row0 * MSF + cb];
                float2 m1 = *(const float2*)&mbuf[(row0 + 8) * MSF + cb];
                float p0 = acc1[mt][nt][0] * m0.x;
                float p1 = acc1[mt][nt][1] * m0.y;
                float p2 = acc1[mt][nt][2] * m1.x;
                float p3 = acc1[mt][nt][3] * m1.y;
                rsum[mt][0] += fabsf(p0) + fabsf(p1);
                rsum[mt][1] += fabsf(p2) + fabsf(p3);
                __half2 ha = __floats2half2_rn(p0, p1);
                __half2 hb = __floats2half2_rn(p2, p3);
                *(uint32_t*)(smem + SM_P + row0 * PSB + cb * 2) = *(uint32_t*)&ha;
                *(uint32_t*)(smem + SM_P + (row0 + 8) * PSB + cb * 2) = *(uint32_t*)&hb;
            }
        }
        __syncthreads();   // P complete; mask[buf] fully consumed

        // ---- GEMM2: O += P @ V  (A from sP, B via ldmatrix.trans on sV) ----
        #pragma unroll
        for (int kk = 0; kk < 4; ++kk) {
            uint32_t p0r[4], p1r[4], vb0[4], vb1[4];
            ldsm_x4(p0r[0], p0r[1], p0r[2], p0r[3], pa_base + kk * 32);
            ldsm_x4(p1r[0], p1r[1], p1r[2], p1r[3], pa_base + 16 * PSB + kk * 32);
            uint32_t vaddr = sVb + (uint32_t)(kk * 16 + lrow) * QSB + d_base * 2 + lchunk;
            ldsm_x4t(vb0[0], vb0[1], vb0[2], vb0[3], vaddr);
            ldsm_x4t(vb1[0], vb1[1], vb1[2], vb1[3], vaddr + 32);
            mma16816(acc2[0][0], p0r[0], p0r[1], p0r[2], p0r[3], vb0[0], vb0[1]);
            mma16816(acc2[0][1], p0r[0], p0r[1], p0r[2], p0r[3], vb0[2], vb0[3]);
            mma16816(acc2[0][2], p0r[0], p0r[1], p0r[2], p0r[3], vb1[0], vb1[1]);
            mma16816(acc2[0][3], p0r[0], p0r[1], p0r[2], p0r[3], vb1[2], vb1[3]);
            mma16816(acc2[1][0], p1r[0], p1r[1], p1r[2], p1r[3], vb0[0], vb0[1]);
            mma16816(acc2[1][1], p1r[0], p1r[1], p1r[2], p1r[3], vb0[2], vb0[3]);
            mma16816(acc2[1][2], p1r[0], p1r[1], p1r[2], p1r[3], vb1[0], vb1[1]);
            mma16816(acc2[1][3], p1r[0], p1r[1], p1r[2], p1r[3], vb1[2], vb1[3]);
        }

        // ---- store staged K/V into the other buffer ----
        if (more) {
            char* dK = smem + SM_K + (buf ^ 1) * 17408;
            char* dV = smem + SM_V + (buf ^ 1) * 17408;
            #pragma unroll
            for (int i = 0; i < 4; ++i) {
                int f = tid + i * NTHREADS;
                int row = f >> 5, d = (f & 31) << 2;
                *(uint2*)(dK + row * QSB + d * 2) = f4h4(kst[i]);
                *(uint2*)(dV + row * QSB + d * 2) = f4h4(vst[i]);
            }
        }
        CPA_WAIT0;
        __syncthreads();
    }

    // ---- r reduction across t (shfl) and the 4 wn groups (smem) ----
    float* sR = (float*)(smem + SM_R);
    #pragma unroll
    for (int mt = 0; mt < 2; ++mt) {
        #pragma unroll
        for (int half = 0; half < 2; ++half) {
            float vv = rsum[mt][half];
            vv += __shfl_xor_sync(0xffffffffu, vv, 1);
            vv += __shfl_xor_sync(0xffffffffu, vv, 2);
            if (t == 0)
                sR[wn * BM + m_base + mt * 16 + half * 8 + g] = vv;
        }
    }
    __syncthreads();

    float* ob = o + ((size_t)(b * HH + h) * SS + s0) * DH;
    #pragma unroll
    for (int mt = 0; mt < 2; ++mt) {
        int row0 = m_base + mt * 16 + g;
        float inv0 = 1.0f / fmaxf(sR[row0] + sR[BM + row0] + sR[2 * BM + row0] + sR[3 * BM + row0], 1.0f);
        int row1 = row0 + 8;
        float inv1 = 1.0f / fmaxf(sR[row1] + sR[BM + row1] + sR[2 * BM + row1] + sR[3 * BM + row1], 1.0f);
        #pragma unroll
        for (int nt = 0; nt < 4; ++nt) {
            int col = d_base + nt * 8 + 2 * t;
            *(float2*)&ob[(size_t)row0 * DH + col] =
                make_float2(acc2[mt][nt][0] * inv0, acc2[mt][nt][1] * inv0);
            *(float2*)&ob[(size_t)row1 * DH + col] =
                make_float2(acc2[mt][nt][2] * inv1, acc2[mt][nt][3] * inv1);
        }
    }
}

extern "C" void kernel_launch(void* const* d_in, const int* in_sizes, int n_in,
                              void* d_out, int out_size) {
    const float* q = (const float*)d_in[0];
    const float* k = (const float*)d_in[1];
    const float* v = (const float*)d_in[2];
    const float* m = (const float*)d_in[3];
    float* o = (float*)d_out;
    cudaFuncSetAttribute(retatt_k4,
                         cudaFuncAttributeMaxDynamicSharedMemorySize, SMEM_BYTES);
    retatt_k4<<<BB * HH * NSTILE, NTHREADS, SMEM_BYTES>>>(q, k, v, m, o);
}

// round 5
// speedup vs baseline: 2.4572x; 1.1096x over previous
#include <cuda_runtime.h>
#include <cuda_fp16.h>
#include <cstdint>

#define BB 2
#define HH 16
#define SS 2048
#define DH 128
#define BM 128
#define BN 64
#define NITER 32
#define NSTILE 16
#define NTHREADS 512

// smem byte layout
#define QSB 272              // Q/K/V row stride (17*16B, ldmatrix conflict-free)
#define MSF 68               // mask row stride in floats (272B)
#define SM_Q 0               // 128*272 = 34816
#define SM_K 34816           // 2 x 64*272 = 17408 each
#define SM_V 69632           // 2 x 17408
#define SM_M 104448          // 2 x 128*272 = 34816 each  (reused as O staging, stride 136 floats)
#define SM_R 174080          // 2*128 floats
#define SMEM_BYTES 175104

// fp16 K/V scratch, filled by conv_kv kernel
__device__ __half KH[BB * HH * SS * DH];
__device__ __half VH[BB * HH * SS * DH];

__device__ __forceinline__ uint32_t smem_u32(const void* p) {
    uint32_t a;
    asm("{ .reg .u64 t; cvta.to.shared.u64 t, %1; cvt.u32.u64 %0, t; }" : "=r"(a) : "l"(p));
    return a;
}
__device__ __forceinline__ void ldsm_x4(uint32_t& r0, uint32_t& r1, uint32_t& r2, uint32_t& r3, uint32_t a) {
    asm volatile("ldmatrix.sync.aligned.m8n8.x4.shared.b16 {%0,%1,%2,%3}, [%4];"
                 : "=r"(r0), "=r"(r1), "=r"(r2), "=r"(r3) : "r"(a));
}
__device__ __forceinline__ void ldsm_x4t(uint32_t& r0, uint32_t& r1, uint32_t& r2, uint32_t& r3, uint32_t a) {
    asm volatile("ldmatrix.sync.aligned.m8n8.x4.trans.shared.b16 {%0,%1,%2,%3}, [%4];"
                 : "=r"(r0), "=r"(r1), "=r"(r2), "=r"(r3) : "r"(a));
}
__device__ __forceinline__ void mma16816(float* c, uint32_t a0, uint32_t a1, uint32_t a2, uint32_t a3,
                                         uint32_t b0, uint32_t b1) {
    asm volatile(
        "mma.sync.aligned.m16n8k16.row.col.f32.f16.f16.f32 "
        "{%0,%1,%2,%3}, {%4,%5,%6,%7}, {%8,%9}, {%0,%1,%2,%3};"
        : "+f"(c[0]), "+f"(c[1]), "+f"(c[2]), "+f"(c[3])
        : "r"(a0), "r"(a1), "r"(a2), "r"(a3), "r"(b0), "r"(b1));
}
__device__ __forceinline__ void cpa16(uint32_t dst, const void* src) {
    asm volatile("cp.async.cg.shared.global [%0], [%1], 16;" :: "r"(dst), "l"(src) : "memory");
}
#define CPA_COMMIT asm volatile("cp.async.commit_group;" ::: "memory")
#define CPA_WAIT0  asm volatile("cp.async.wait_group 0;" ::: "memory")

__device__ __forceinline__ uint2 f4h4(float4 v) {
    __half2 a = __floats2half2_rn(v.x, v.y);
    __half2 b = __floats2half2_rn(v.z, v.w);
    uint2 w;
    w.x = *(uint32_t*)&a;
    w.y = *(uint32_t*)&b;
    return w;
}
__device__ __forceinline__ uint32_t packh2(float a, float b) {
    __half2 h = __floats2half2_rn(a, b);
    return *(uint32_t*)&h;
}

// ---- pre-convert K,V fp32 -> fp16 scratch ----
__global__ __launch_bounds__(512, 2)
void conv_kv(const float* __restrict__ k, const float* __restrict__ v) {
    int i = blockIdx.x * blockDim.x + threadIdx.x;   // over float4 groups
    ((uint2*)KH)[i] = f4h4(((const float4*)k)[i]);
    ((uint2*)VH)[i] = f4h4(((const float4*)v)[i]);
}

__global__ __launch_bounds__(NTHREADS, 1)
void retatt_k5(const float* __restrict__ q, const float* __restrict__ mask,
               float* __restrict__ o)
{
    extern __shared__ char smem[];
    const uint32_t sbase = smem_u32(smem);
    const int tid = threadIdx.x;
    const int wid = tid >> 5;
    const int lane = tid & 31;
    const int g = lane >> 2;
    const int t = lane & 3;
    const int wm = wid >> 1;            // 0..7 : 16-row M strip
    const int wn = wid & 1;             // 0..1 : 32-col K-slice (split-k for GEMM2)
    const int m_base = wm * 16;
    const int n_base = wn * 32;
    const int lrow = lane & 15;
    const int lchunk = (lane >> 4) * 16;

    const int bid = blockIdx.x;
    const int b  = bid & 1;
    const int r_ = bid >> 1;
    const int h  = r_ / NSTILE;
    const int st = r_ % NSTILE;
    const int s0 = st * BM;

    const float* qbase = q + ((size_t)(b * HH + h) * SS + s0) * DH;
    const __half* khb = KH + ((size_t)(b * HH + h) * SS) * DH;
    const __half* vhb = VH + ((size_t)(b * HH + h) * SS) * DH;
    const float* mbase = mask + ((size_t)h * SS + s0) * SS;

    // ---- prologue: Q fp16 (LDG+cvt+STS), K0/V0/mask0 via cp.async ----
    {
        const float4* gq = (const float4*)qbase;
        #pragma unroll
        for (int i = 0; i < 8; ++i) {
            int f = tid + i * NTHREADS;
            int row = f >> 5, d = (f & 31) << 2;
            *(uint2*)(smem + SM_Q + row * QSB + d * 2) = f4h4(gq[f]);
        }
        #pragma unroll
        for (int i = 0; i < 2; ++i) {                 // K0, V0: 1024 x 16B each
            int f = tid + i * NTHREADS;
            int row = f >> 4, c16 = f & 15;
            cpa16(sbase + SM_K + row * QSB + c16 * 16, khb + row * DH + c16 * 8);
            cpa16(sbase + SM_V + row * QSB + c16 * 16, vhb + row * DH + c16 * 8);
        }
        #pragma unroll
        for (int i = 0; i < 4; ++i) {                 // mask0: 2048 x 16B
            int f = tid + i * NTHREADS;
            int row = f >> 4, c = (f & 15) << 2;
            cpa16(sbase + SM_M + row * QSB + c * 4, mbase + (size_t)row * SS + c);
        }
        CPA_COMMIT;
        CPA_WAIT0;
        __syncthreads();
    }

    float acc2[16][4];
    #pragma unroll
    for (int nt = 0; nt < 16; ++nt)
        #pragma unroll
        for (int i = 0; i < 4; ++i) acc2[nt][i] = 0.f;
    float rsum[2] = {0.f, 0.f};

    const uint32_t qa = sbase + SM_Q + (uint32_t)(m_base + lrow) * QSB + lchunk;

    #pragma unroll 2
    for (int it = 0; it < NITER; ++it) {
        const int buf = it & 1;
        const uint32_t sKb = sbase + SM_K + buf * 17408;
        const uint32_t sVb = sbase + SM_V + buf * 17408;
        const float* mbuf = (const float*)(smem + SM_M + buf * 34816);

        // ---- issue next-tile cp.async (K, V, mask) into buf^1 ----
        if (it + 1 < NITER) {
            const int t1 = (it + 1) * BN;
            const uint32_t kd = sbase + SM_K + (buf ^ 1) * 17408;
            const uint32_t vd = sbase + SM_V + (buf ^ 1) * 17408;
            #pragma unroll
            for (int i = 0; i < 2; ++i) {
                int f = tid + i * NTHREADS;
                int row = f >> 4, c16 = f & 15;
                cpa16(kd + row * QSB + c16 * 16, khb + (size_t)(t1 + row) * DH + c16 * 8);
                cpa16(vd + row * QSB + c16 * 16, vhb + (size_t)(t1 + row) * DH + c16 * 8);
            }
            const uint32_t md = sbase + SM_M + (buf ^ 1) * 34816;
            #pragma unroll
            for (int i = 0; i < 4; ++i) {
                int f = tid + i * NTHREADS;
                int row = f >> 4, c = (f & 15) << 2;
                cpa16(md + row * QSB + c * 4, mbase + (size_t)row * SS + t1 + c);
            }
            CPA_COMMIT;
        }

        // ---- GEMM1: S[16 rows x 32 cols] per warp = Q @ K^T ----
        float acc1[4][4];
        #pragma unroll
        for (int nt = 0; nt < 4; ++nt)
            #pragma unroll
            for (int i = 0; i < 4; ++i) acc1[nt][i] = 0.f;

        const uint32_t kb0 = sKb + (uint32_t)(n_base + lrow) * QSB + lchunk;
        #pragma unroll
        for (int kk = 0; kk < 8; ++kk) {
            uint32_t a0, a1, a2, a3, b0, b1, b2, b3, c0, c1, c2, c3;
            ldsm_x4(a0, a1, a2, a3, qa + kk * 32);
            ldsm_x4(b0, b1, b2, b3, kb0 + kk * 32);
            ldsm_x4(c0, c1, c2, c3, kb0 + 16 * QSB + kk * 32);
            mma16816(acc1[0], a0, a1, a2, a3, b0, b2);
            mma16816(acc1[1], a0, a1, a2, a3, b1, b3);
            mma16816(acc1[2], a0, a1, a2, a3, c0, c2);
            mma16816(acc1[3], a0, a1, a2, a3, c1, c3);
        }

        // ---- epilogue in registers: P = S*mask, rsum += |P|, pack A-frags ----
        uint32_t A0[4], A1[4];   // GEMM2 A fragments for k-blocks 0,1 of this warp's slice
        {
            uint32_t h01[4], h23[4];
            #pragma unroll
            for (int nt = 0; nt < 4; ++nt) {
                const int row0 = m_base + g;
                const int cb = n_base + nt * 8 + 2 * t;
                float2 m0 = *(const float2*)&mbuf[row0 * MSF + cb];
                float2 m1 = *(const float2*)&mbuf[(row0 + 8) * MSF + cb];
                float p0 = acc1[nt][0] * m0.x;
                float p1 = acc1[nt][1] * m0.y;
                float p2 = acc1[nt][2] * m1.x;
                float p3 = acc1[nt][3] * m1.y;
                rsum[0] += fabsf(p0) + fabsf(p1);
                rsum[1] += fabsf(p2) + fabsf(p3);
                h01[nt] = packh2(p0, p1);
                h23[nt] = packh2(p2, p3);
            }
            A0[0] = h01[0]; A0[1] = h23[0]; A0[2] = h01[1]; A0[3] = h23[1];
            A1[0] = h01[2]; A1[1] = h23[2]; A1[2] = h01[3]; A1[3] = h23[3];
        }

        // ---- GEMM2 (split-k): O_partial += P_slice @ V_slice, all 128 d-cols ----
        #pragma unroll
        for (int kb = 0; kb < 2; ++kb) {
            const uint32_t vrow = sVb + (uint32_t)(n_base + kb * 16 + lrow) * QSB + lchunk;
            #pragma unroll
            for (int dc = 0; dc < 8; ++dc) {
                uint32_t v0, v1, v2, v3;
                ldsm_x4t(v0, v1, v2, v3, vrow + dc * 32);
                if (kb == 0) {
                    mma16816(acc2[2 * dc],     A0[0], A0[1], A0[2], A0[3], v0, v1);
                    mma16816(acc2[2 * dc + 1], A0[0], A0[1], A0[2], A0[3], v2, v3);
                } else {
                    mma16816(acc2[2 * dc],     A1[0], A1[1], A1[2], A1[3], v0, v1);
                    mma16816(acc2[2 * dc + 1], A1[0], A1[1], A1[2], A1[3], v2, v3);
                }
            }
        }

        CPA_WAIT0;
        __syncthreads();
    }

    // ---- r reduction: quad shfl, then across the 2 wn slices via smem ----
    float* sR = (float*)(smem + SM_R);
    #pragma unroll
    for (int half = 0; half < 2; ++half) {
        float vv = rsum[half];
        vv += __shfl_xor_sync(0xffffffffu, vv, 1);
        vv += __shfl_xor_sync(0xffffffffu, vv, 2);
        if (t == 0) sR[wn * BM + m_base + half * 8 + g] = vv;
    }

    // ---- O split-k reduction: wn=0 stages to smem; wn=1 adds + scales + stores ----
    float* ost = (float*)(smem + SM_M);   // stride 136 floats, reuses mask region
    if (wn == 0) {
        #pragma unroll
        for (int nt = 0; nt < 16; ++nt) {
            const int row0 = m_base + g;
            const int cb = nt * 8 + 2 * t;
            *(float2*)&ost[row0 * 136 + cb] = make_float2(acc2[nt][0], acc2[nt][1]);
            *(float2*)&ost[(row0 + 8) * 136 + cb] = make_float2(acc2[nt][2], acc2[nt][3]);
        }
    }
    __syncthreads();

    if (wn == 1) {
        float* ob = o + ((size_t)(b * HH + h) * SS + s0) * DH;
        const int row0 = m_base + g;
        const int row1 = row0 + 8;
        const float inv0 = 1.0f / fmaxf(sR[row0] + sR[BM + row0], 1.0f);
        const float inv1 = 1.0f / fmaxf(sR[row1] + sR[BM + row1], 1.0f);
        #pragma unroll
        for (int nt = 0; nt < 16; ++nt) {
            const int cb = nt * 8 + 2 * t;
            float2 s0 = *(const float2*)&ost[row0 * 136 + cb];
            float2 s1 = *(const float2*)&ost[row1 * 136 + cb];
            *(float2*)&ob[(size_t)row0 * DH + cb] =
                make_float2((s0.x + acc2[nt][0]) * inv0, (s0.y + acc2[nt][1]) * inv0);
            *(float2*)&ob[(size_t)row1 * DH + cb] =
                make_float2((s1.x + acc2[nt][2]) * inv1, (s1.y + acc2[nt][3]) * inv1);
        }
    }
}

extern "C" void kernel_launch(void* const* d_in, const int* in_sizes, int n_in,
                              void* d_out, int out_size) {
    const float* q = (const float*)d_in[0];
    const float* k = (const float*)d_in[1];
    const float* v = (const float*)d_in[2];
    const float* m = (const float*)d_in[3];
    float* o = (float*)d_out;
    conv_kv<<<(BB * HH * SS * DH / 4) / 512, 512>>>(k, v);
    cudaFuncSetAttribute(retatt_k5,
                         cudaFuncAttributeMaxDynamicSharedMemorySize, SMEM_BYTES);
    retatt_k5<<<BB * HH * NSTILE, NTHREADS, SMEM_BYTES>>>(q, m, o);
}